// round 16
// baseline (speedup 1.0000x reference)
#include <cuda_runtime.h>
#include <cuda_fp16.h>
#include <cstdint>

#define BN 8
#define NN 4096
#define DD 256
#define SAMPK 256
#define KHL 512          // stored halfs per row: [hi | lo]
#define NCH 12           // K chunks of 64 (hi.hi x4, hi.lo x4, lo.hi x4)
#define NSTRIPE 528      // upper-triangle 128x128 tiles per batch
#define STAGE_B 32768
#define KNN_SMEM (3 * STAGE_B)
#define BUF_STRIDE 129
#define SCHUNK 1024      // sort phase-1 chunk size
#define NCHUNK (NN / SCHUNK)

// ---------------- scratch (no allocations allowed) ----------------
__device__ float g_sq[BN * NN];
__device__ float g_dk2[BN * NN];
__device__ int   g_sidx[BN * SAMPK];
__device__ __half g_x16[(size_t)BN * NN * KHL];
__device__ float g_part[(size_t)64 * BN * NN * 5];   // slot-major: [slot][b*NN+row][5]
__device__ unsigned long long g_cand[BN * NCHUNK * SAMPK];

// ---------------- kernel A: fused fp32 -> fp16 hi/lo split + sum of squares ----------------
__global__ void cvtsq_kernel(const float* __restrict__ x) {
    const int row = blockIdx.x * 8 + (threadIdx.x >> 5);
    const int lane = threadIdx.x & 31;
    const float4* p = (const float4*)(x + (size_t)row * DD);
    unsigned short* xp = (unsigned short*)g_x16 + (size_t)row * KHL;
    float s = 0.f;
#pragma unroll
    for (int i = 0; i < 2; i++) {
        float4 v = p[lane + i * 32];
        float f[4] = {v.x, v.y, v.z, v.w};
        __half h[4], l[4];
#pragma unroll
        for (int k = 0; k < 4; k++) {
            h[k] = __float2half_rn(f[k]);
            l[k] = __float2half_rn(f[k] - __half2float(h[k]));
        }
        uint2 uh = make_uint2(
            (uint32_t)__half_as_ushort(h[0]) | ((uint32_t)__half_as_ushort(h[1]) << 16),
            (uint32_t)__half_as_ushort(h[2]) | ((uint32_t)__half_as_ushort(h[3]) << 16));
        uint2 ul = make_uint2(
            (uint32_t)__half_as_ushort(l[0]) | ((uint32_t)__half_as_ushort(l[1]) << 16),
            (uint32_t)__half_as_ushort(l[2]) | ((uint32_t)__half_as_ushort(l[3]) << 16));
        int kk = lane * 4 + i * 128;
        *(uint2*)(xp + kk)       = uh;
        *(uint2*)(xp + 256 + kk) = ul;
        s = fmaf(v.x, v.x, fmaf(v.y, v.y, fmaf(v.z, v.z, fmaf(v.w, v.w, s))));
    }
#pragma unroll
    for (int o = 16; o; o >>= 1) s += __shfl_xor_sync(0xffffffffu, s, o);
    if (lane == 0) g_sq[row] = s;
}

// ---------------- mma helpers ----------------
__device__ __forceinline__ void ldmx4(uint32_t* r, uint32_t addr) {
    asm volatile("ldmatrix.sync.aligned.m8n8.x4.shared.b16 {%0,%1,%2,%3}, [%4];"
                 : "=r"(r[0]), "=r"(r[1]), "=r"(r[2]), "=r"(r[3]) : "r"(addr));
}
__device__ __forceinline__ void mma16816(float* d, const uint32_t* a, const uint32_t* b) {
    asm volatile("mma.sync.aligned.m16n8k16.row.col.f32.f16.f16.f32 "
                 "{%0,%1,%2,%3}, {%4,%5,%6,%7}, {%8,%9}, {%0,%1,%2,%3};"
                 : "+f"(d[0]), "+f"(d[1]), "+f"(d[2]), "+f"(d[3])
                 : "r"(a[0]), "r"(a[1]), "r"(a[2]), "r"(a[3]), "r"(b[0]), "r"(b[1]));
}
__device__ __forceinline__ void cp16(uint32_t dst, const void* src) {
    asm volatile("cp.async.cg.shared.global [%0], [%1], 16;" :: "r"(dst), "l"(src) : "memory");
}
__device__ __forceinline__ void ins5(float* t, float v) {
    if (v < t[4]) {
        float mm = v;
#pragma unroll
        for (int q = 0; q < 5; q++) {
            float cur = t[q];
            float lo = fminf(mm, cur);
            mm = fmaxf(mm, cur);
            t[q] = lo;
        }
    }
}

// ---------------- kernel C: symmetric mma.sync GEMM + fused kNN top-5 ----------------
// grid (528 upper-tri 128x128 tiles, 8 batches), 128 threads = 4 warps (2M x 2N),
// warp tile 64x64 (halves duplicate ldmatrix traffic), K chunks of 64,
// 3-stage cp.async, 2 blocks/SM.
__global__ void __launch_bounds__(128, 2) knn_sym_kernel() {
    extern __shared__ __align__(128) char sm[];
    uint32_t smb;
    asm("{ .reg .u64 t; cvta.to.shared.u64 t, %1; cvt.u32.u64 %0, t; }" : "=r"(smb) : "l"(sm));

    const int tid = threadIdx.x;
    const int lane = tid & 31;
    const int warp = tid >> 5;
    const int wm = warp & 1;       // 0..1 (M, 64 rows each)
    const int wn = warp >> 1;      // 0..1 (N, 64 cols each)
    const int b  = blockIdx.y;

    // decode tile index -> (I, J), J >= I
    int I = 0;
    int s = blockIdx.x;
    while (s >= 32 - I) { s -= 32 - I; I++; }
    const int J = I + s;
    const int i0 = I * 128;
    const int j0 = J * 128;

    // loader: 16 x 16B per thread; u = tid + k*128, row = u>>3 (+16/k), q = tid&7 const
    const int lr = tid >> 3;
    const int lq = tid & 7;
    const uint32_t soff0 = (uint32_t)(lr * 128 + ((lq ^ (lr & 7)) * 16));   // swizzle k-invariant
    const __half* baseA = g_x16 + ((size_t)(b * NN + i0 + lr)) * KHL + lq * 8;
    const __half* baseB = g_x16 + ((size_t)(b * NN + j0 + lr)) * KHL + lq * 8;

    auto issue = [&](int c) {
        const int ka = (c & 3) * 64 + ((c >= 8) ? 256 : 0);              // A: hi,hi,lo
        const int kb = (c & 3) * 64 + ((c >= 4 && c < 8) ? 256 : 0);     // B: hi,lo,hi
        const uint32_t base = smb + (c % 3) * STAGE_B;
#pragma unroll
        for (int k = 0; k < 8; k++)
            cp16(base + soff0 + k * 2048, baseA + (size_t)k * 16 * KHL + ka);
#pragma unroll
        for (int k = 0; k < 8; k++)
            cp16(base + 16384 + soff0 + k * 2048, baseB + (size_t)k * 16 * KHL + kb);
        asm volatile("cp.async.commit_group;" ::: "memory");
    };

    float acc[4][8][4];
#pragma unroll
    for (int mi = 0; mi < 4; mi++)
#pragma unroll
        for (int ni = 0; ni < 8; ni++)
#pragma unroll
            for (int v = 0; v < 4; v++) acc[mi][ni][v] = 0.f;

    issue(0); issue(1);

    for (int c = 0; c < NCH; c++) {
        if (c < NCH - 1) asm volatile("cp.async.wait_group 1;" ::: "memory");
        else             asm volatile("cp.async.wait_group 0;" ::: "memory");
        __syncthreads();
        if (c + 2 < NCH) issue(c + 2);

        const uint32_t Ab = smb + (c % 3) * STAGE_B;
        const uint32_t Bb = Ab + 16384;

#pragma unroll
        for (int k16 = 0; k16 < 4; k16++) {
            uint32_t afr[4][4], bfr[8][2];
#pragma unroll
            for (int mi = 0; mi < 4; mi++) {
                int R = wm * 64 + mi * 16 + (lane & 15);
                int ul = k16 * 2 + (lane >> 4);
                ldmx4(afr[mi], Ab + R * 128 + ((ul ^ (R & 7)) * 16));
            }
#pragma unroll
            for (int np = 0; np < 4; np++) {
                int RB = wn * 64 + np * 16 + ((lane >> 4) << 3) + (lane & 7);
                int ul = k16 * 2 + ((lane >> 3) & 1);
                uint32_t r[4];
                ldmx4(r, Bb + RB * 128 + ((ul ^ (RB & 7)) * 16));
                bfr[np * 2][0] = r[0]; bfr[np * 2][1] = r[1];
                bfr[np * 2 + 1][0] = r[2]; bfr[np * 2 + 1][1] = r[3];
            }
#pragma unroll
            for (int mi = 0; mi < 4; mi++)
#pragma unroll
                for (int ni = 0; ni < 8; ni++)
                    mma16816(acc[mi][ni], afr[mi], bfr[ni]);
        }
        // no trailing barrier — next iteration's post-wait __syncthreads orders stage reuse
    }

    // ---- row fold: rows of tile I over all 128 cols of tile J ----
    int gi[8]; float sqi[8];
#pragma unroll
    for (int mi = 0; mi < 4; mi++)
#pragma unroll
        for (int h = 0; h < 2; h++) {
            int s2 = mi * 2 + h;
            gi[s2] = i0 + wm * 64 + mi * 16 + (lane >> 2) + h * 8;
            sqi[s2] = g_sq[b * NN + gi[s2]];
        }
    float t5[8][5];
#pragma unroll
    for (int s2 = 0; s2 < 8; s2++)
#pragma unroll
        for (int q = 0; q < 5; q++) t5[s2][q] = INFINITY;

#pragma unroll
    for (int ni = 0; ni < 8; ni++)
#pragma unroll
        for (int cc = 0; cc < 2; cc++) {
            int gj = j0 + wn * 64 + ni * 8 + (lane & 3) * 2 + cc;
            float sqj = __ldg(&g_sq[b * NN + gj]);
#pragma unroll
            for (int mi = 0; mi < 4; mi++)
#pragma unroll
                for (int h = 0; h < 2; h++) {
                    int s2 = mi * 2 + h;
                    float G = acc[mi][ni][h * 2 + cc];
                    float v = __fsub_rn(__fadd_rn(sqi[s2], sqj), __fmul_rn(2.0f, G));
                    v = fmaxf(v, 0.0f);
                    if (gj == gi[s2]) v = INFINITY;
                    ins5(t5[s2], v);
                }
        }

    // ---- merge 8 owners per row, write g_part slot J ----
    __syncthreads();   // all warps done reading smem stages before reuse
    float* MS = (float*)sm;   // 128 rows x 8 owners x 5 = 20KB
    const int owner = wn * 4 + (lane & 3);
#pragma unroll
    for (int s2 = 0; s2 < 8; s2++) {
        int rloc = gi[s2] - i0;
#pragma unroll
        for (int q = 0; q < 5; q++) MS[rloc * 40 + owner * 5 + q] = t5[s2][q];
    }
    __syncthreads();
    {
        float best[5] = {INFINITY, INFINITY, INFINITY, INFINITY, INFINITY};
        for (int k = 0; k < 40; k++) ins5(best, MS[tid * 40 + k]);
        size_t o = ((size_t)J * BN * NN + (size_t)(b * NN + i0 + tid)) * 5;
#pragma unroll
        for (int q = 0; q < 5; q++) g_part[o + q] = best[q];
    }

    // ---- column fold (off-diagonal only): per-column top-5 over 128 rows ----
    if (J > I) {
        __syncthreads();
        float* BUF = (float*)sm;           // [128 cols][129]
#pragma unroll
        for (int ni = 0; ni < 8; ni++)
#pragma unroll
            for (int cc = 0; cc < 2; cc++) {
                int cl = wn * 64 + ni * 8 + (lane & 3) * 2 + cc;
                int gj = j0 + cl;
                float sqj = __ldg(&g_sq[b * NN + gj]);
#pragma unroll
                for (int mi = 0; mi < 4; mi++)
#pragma unroll
                    for (int h = 0; h < 2; h++) {
                        int s2 = mi * 2 + h;
                        int rl = gi[s2] - i0;
                        float G = acc[mi][ni][h * 2 + cc];
                        float v = __fsub_rn(__fadd_rn(sqi[s2], sqj), __fmul_rn(2.0f, G));
                        v = fmaxf(v, 0.0f);
                        BUF[cl * BUF_STRIDE + rl] = v;
                    }
            }
        __syncthreads();
        {
            float best[5] = {INFINITY, INFINITY, INFINITY, INFINITY, INFINITY};
            const float* bp = BUF + tid * BUF_STRIDE;
            for (int r = 0; r < 128; r++) ins5(best, bp[r]);
            size_t o = ((size_t)(32 + I) * BN * NN + (size_t)(b * NN + j0 + tid)) * 5;
#pragma unroll
            for (int q = 0; q < 5; q++) g_part[o + q] = best[q];
        }
    }
}

// ---------------- kernel C2: merge partial top-5 lists (4 threads/row + shfl) ----------------
__global__ void merge_kernel() {
    int t = blockIdx.x * 256 + threadIdx.x;
    int r = t >> 2;                 // b*NN + i
    int par = t & 3;
    int i = r & (NN - 1);
    int T = i >> 7;
    float best[5] = {INFINITY, INFINITY, INFINITY, INFINITY, INFINITY};
    // 32 live slots: k<32-T -> row-fold slot T+k ; else col-fold slot 32+(k-(32-T))
    for (int k = par; k < 32; k += 4) {
        int slot = (k < 32 - T) ? (T + k) : (32 + k - (32 - T));
        size_t o = ((size_t)slot * BN * NN + r) * 5;
#pragma unroll
        for (int q = 0; q < 5; q++) ins5(best, g_part[o + q]);
    }
    float ob[5];
#pragma unroll
    for (int q = 0; q < 5; q++) ob[q] = __shfl_xor_sync(0xffffffffu, best[q], 1);
#pragma unroll
    for (int q = 0; q < 5; q++) ins5(best, ob[q]);
#pragma unroll
    for (int q = 0; q < 5; q++) ob[q] = __shfl_xor_sync(0xffffffffu, best[q], 2);
#pragma unroll
    for (int q = 0; q < 5; q++) ins5(best, ob[q]);
    if (par == 0) g_dk2[r] = best[4];
}

// ---------------- threefry2x32, key = (0, 42) ----------------
__device__ __forceinline__ uint2 threefry_0_42(unsigned x0, unsigned x1) {
    const unsigned ks0 = 0u, ks1 = 42u;
    const unsigned ks2 = 0x1BD11BDAu ^ 42u;
    x0 += ks0; x1 += ks1;
#define ROTL(v, d) (((v) << (d)) | ((v) >> (32 - (d))))
#define RND(r) { x0 += x1; x1 = ROTL(x1, r); x1 ^= x0; }
    RND(13) RND(15) RND(26) RND(6)  x0 += ks1; x1 += ks2 + 1u;
    RND(17) RND(29) RND(16) RND(24) x0 += ks2; x1 += ks0 + 2u;
    RND(13) RND(15) RND(26) RND(6)  x0 += ks0; x1 += ks1 + 3u;
    RND(17) RND(29) RND(16) RND(24) x0 += ks1; x1 += ks2 + 4u;
    RND(13) RND(15) RND(26) RND(6)  x0 += ks2; x1 += ks0 + 5u;
#undef RND
#undef ROTL
    return make_uint2(x0, x1);
}

// ---------------- kernel D1: per-chunk scores + top-256 candidates ----------------
__global__ void score_chunk_kernel() {
    __shared__ unsigned long long keys[SCHUNK];
    const int b = blockIdx.y;
    const int ch = blockIdx.x;
    const int tid = threadIdx.x; // 512
    const float TINY = 1.17549435e-38f;

    for (int t = tid; t < SCHUNK; t += 512) {
        int n = ch * SCHUNK + t;
        int jf = b * NN + n;
        uint2 y = threefry_0_42(0u, (unsigned)jf);
        unsigned bits = y.x ^ y.y;
        float u = __uint_as_float((bits >> 9) | 0x3f800000u) - 1.0f;
        float val = fmaxf(TINY, __fadd_rn(u, TINY));
        float g = -logf(-logf(val));
        float w = sqrtf(__fadd_rn(g_dk2[jf], 1e-12f));
        float score = __fadd_rn(logf(__fadd_rn(w, 1e-12f)), g);
        unsigned sb = __float_as_uint(score);
        unsigned mono = (sb & 0x80000000u) ? ~sb : (sb | 0x80000000u);
        keys[t] = ((unsigned long long)(~mono) << 32) | (unsigned)n;  // asc = desc score, ties -> low idx
    }
    __syncthreads();

    for (int k = 2; k <= SCHUNK; k <<= 1) {
        for (int j = k >> 1; j > 0; j >>= 1) {
            for (int i = tid; i < SCHUNK; i += 512) {
                int ixj = i ^ j;
                if (ixj > i) {
                    bool up = ((i & k) == 0);
                    unsigned long long a = keys[i], c = keys[ixj];
                    if ((a > c) == up) { keys[i] = c; keys[ixj] = a; }
                }
            }
            __syncthreads();
        }
    }
    if (tid < SAMPK) g_cand[(b * NCHUNK + ch) * SAMPK + tid] = keys[tid];
}

// ---------------- kernel D2: merge candidates, final top-256 ----------------
__global__ void final_sort_kernel() {
    __shared__ unsigned long long keys[NCHUNK * SAMPK];  // 1024
    const int b = blockIdx.x;
    const int tid = threadIdx.x; // 512
    const int NC = NCHUNK * SAMPK;

    for (int t = tid; t < NC; t += 512) keys[t] = g_cand[b * NC + t];
    __syncthreads();

    for (int k = 2; k <= NC; k <<= 1) {
        for (int j = k >> 1; j > 0; j >>= 1) {
            for (int i = tid; i < NC; i += 512) {
                int ixj = i ^ j;
                if (ixj > i) {
                    bool up = ((i & k) == 0);
                    unsigned long long a = keys[i], c = keys[ixj];
                    if ((a > c) == up) { keys[i] = c; keys[ixj] = a; }
                }
            }
            __syncthreads();
        }
    }
    if (tid < SAMPK) g_sidx[b * SAMPK + tid] = (int)(keys[tid] & 0xffffffffu);
}

// ---------------- kernel E: vectorized gather + tail zero ----------------
__global__ void gather_kernel(const float* __restrict__ x, float* __restrict__ out, int out_size) {
    const long SAMPV = (long)BN * SAMPK * DD / 4;   // float4 count
    long gid = (long)blockIdx.x * 256 + threadIdx.x;
    if (gid < SAMPV) {
        int d4 = (int)(gid & 63);
        int samp = (int)(gid >> 6);          // bb*256 + s
        int s = samp & 255;
        int bb = samp >> 8;
        int idx = g_sidx[bb * SAMPK + s];
        float4 v = *(const float4*)(x + ((size_t)bb * NN + idx) * DD + d4 * 4);
        *(float4*)(out + gid * 4) = v;
    } else {
        long t = (long)BN * SAMPK * DD + (gid - SAMPV);
        if (t < out_size) out[t] = 0.0f;
    }
}

// ---------------- launch ----------------
extern "C" void kernel_launch(void* const* d_in, const int* in_sizes, int n_in,
                              void* d_out, int out_size) {
    const float* x = (const float*)d_in[0];
    float* out = (float*)d_out;

    static bool configured = false;
    if (!configured) {
        cudaFuncSetAttribute(knn_sym_kernel, cudaFuncAttributeMaxDynamicSharedMemorySize, KNN_SMEM);
        configured = true;
    }

    cvtsq_kernel<<<BN * NN / 8, 256>>>(x);

    dim3 g1(NSTRIPE, BN);
    knn_sym_kernel<<<g1, 128, KNN_SMEM>>>();

    merge_kernel<<<BN * NN * 4 / 256, 256>>>();

    dim3 gs(NCHUNK, BN);
    score_chunk_kernel<<<gs, 512>>>();
    final_sort_kernel<<<BN, 512>>>();

    long samp = (long)BN * SAMPK * DD;
    long work = samp / 4 + (out_size > samp ? out_size - samp : 0);
    gather_kernel<<<(unsigned)((work + 255) / 256), 256>>>(x, out, out_size);
}

// round 17
// speedup vs baseline: 1.1118x; 1.1118x over previous
#include <cuda_runtime.h>
#include <cuda_fp16.h>
#include <cstdint>

#define BN 8
#define NN 4096
#define DD 256
#define SAMPK 256
#define KHL 512          // stored halfs per row: [hi | lo]
#define NCH 12           // K chunks of 64 (hi.hi x4, hi.lo x4, lo.hi x4)
#define NSTRIPE 528      // upper-triangle 128x128 tiles per batch
#define STAGE_B 32768
#define KNN_SMEM (3 * STAGE_B)
#define BUF_STRIDE 129
#define CM_OFF 66048     // after BUF (128*129*4)
#define SCHUNK 1024      // sort phase-1 chunk size
#define NCHUNK (NN / SCHUNK)

// ---------------- scratch (no allocations allowed) ----------------
__device__ float g_sq[BN * NN];
__device__ float g_dk2[BN * NN];
__device__ int   g_sidx[BN * SAMPK];
__device__ __half g_x16[(size_t)BN * NN * KHL];
__device__ float g_part[(size_t)64 * BN * NN * 5];   // slot-major: [slot][b*NN+row][5]
__device__ unsigned long long g_cand[BN * NCHUNK * SAMPK];

// ---------------- kernel A: fused fp32 -> fp16 hi/lo split + sum of squares ----------------
__global__ void cvtsq_kernel(const float* __restrict__ x) {
    const int row = blockIdx.x * 8 + (threadIdx.x >> 5);
    const int lane = threadIdx.x & 31;
    const float4* p = (const float4*)(x + (size_t)row * DD);
    unsigned short* xp = (unsigned short*)g_x16 + (size_t)row * KHL;
    float s = 0.f;
#pragma unroll
    for (int i = 0; i < 2; i++) {
        float4 v = p[lane + i * 32];
        float f[4] = {v.x, v.y, v.z, v.w};
        __half h[4], l[4];
#pragma unroll
        for (int k = 0; k < 4; k++) {
            h[k] = __float2half_rn(f[k]);
            l[k] = __float2half_rn(f[k] - __half2float(h[k]));
        }
        uint2 uh = make_uint2(
            (uint32_t)__half_as_ushort(h[0]) | ((uint32_t)__half_as_ushort(h[1]) << 16),
            (uint32_t)__half_as_ushort(h[2]) | ((uint32_t)__half_as_ushort(h[3]) << 16));
        uint2 ul = make_uint2(
            (uint32_t)__half_as_ushort(l[0]) | ((uint32_t)__half_as_ushort(l[1]) << 16),
            (uint32_t)__half_as_ushort(l[2]) | ((uint32_t)__half_as_ushort(l[3]) << 16));
        int kk = lane * 4 + i * 128;
        *(uint2*)(xp + kk)       = uh;
        *(uint2*)(xp + 256 + kk) = ul;
        s = fmaf(v.x, v.x, fmaf(v.y, v.y, fmaf(v.z, v.z, fmaf(v.w, v.w, s))));
    }
#pragma unroll
    for (int o = 16; o; o >>= 1) s += __shfl_xor_sync(0xffffffffu, s, o);
    if (lane == 0) g_sq[row] = s;
}

// ---------------- mma helpers ----------------
__device__ __forceinline__ void ldmx4(uint32_t* r, uint32_t addr) {
    asm volatile("ldmatrix.sync.aligned.m8n8.x4.shared.b16 {%0,%1,%2,%3}, [%4];"
                 : "=r"(r[0]), "=r"(r[1]), "=r"(r[2]), "=r"(r[3]) : "r"(addr));
}
__device__ __forceinline__ void mma16816(float* d, const uint32_t* a, const uint32_t* b) {
    asm volatile("mma.sync.aligned.m16n8k16.row.col.f32.f16.f16.f32 "
                 "{%0,%1,%2,%3}, {%4,%5,%6,%7}, {%8,%9}, {%0,%1,%2,%3};"
                 : "+f"(d[0]), "+f"(d[1]), "+f"(d[2]), "+f"(d[3])
                 : "r"(a[0]), "r"(a[1]), "r"(a[2]), "r"(a[3]), "r"(b[0]), "r"(b[1]));
}
__device__ __forceinline__ void cp16(uint32_t dst, const void* src) {
    asm volatile("cp.async.cg.shared.global [%0], [%1], 16;" :: "r"(dst), "l"(src) : "memory");
}
__device__ __forceinline__ void ins5(float* t, float v) {
    if (v < t[4]) {
        float mm = v;
#pragma unroll
        for (int q = 0; q < 5; q++) {
            float cur = t[q];
            float lo = fminf(mm, cur);
            mm = fmaxf(mm, cur);
            t[q] = lo;
        }
    }
}

// ---------------- kernel C: symmetric mma.sync GEMM + fused kNN top-5 ----------------
// grid (528 upper-tri 128x128 tiles, 8 batches), 256 threads = 8 warps (4M x 2N),
// warp tile 32x64, K chunks of 64, 3-stage cp.async, 2 blocks/SM.
__global__ void __launch_bounds__(256, 2) knn_sym_kernel() {
    extern __shared__ __align__(128) char sm[];
    uint32_t smb;
    asm("{ .reg .u64 t; cvta.to.shared.u64 t, %1; cvt.u32.u64 %0, t; }" : "=r"(smb) : "l"(sm));

    const int tid = threadIdx.x;
    const int lane = tid & 31;
    const int warp = tid >> 5;
    const int wm = warp & 3;       // 0..3 (M, 32 rows each)
    const int wn = warp >> 2;      // 0..1 (N, 64 cols each)
    const int b  = blockIdx.y;

    // decode tile index -> (I, J), J >= I
    int I = 0;
    int s = blockIdx.x;
    while (s >= 32 - I) { s -= 32 - I; I++; }
    const int J = I + s;
    const int i0 = I * 128;
    const int j0 = J * 128;

    // loader precompute: 8 x 16B per thread; rows = tid>>3 + k*32 (k<4: A, k>=4: B)
    const int lr = tid >> 3;
    const int lq = tid & 7;
    const uint32_t soff0 = (uint32_t)(lr * 128 + ((lq ^ (lr & 7)) * 16));
    const __half* baseA = g_x16 + ((size_t)(b * NN + i0 + lr)) * KHL + lq * 8;
    const __half* baseB = g_x16 + ((size_t)(b * NN + j0 + lr)) * KHL + lq * 8;

    auto issue = [&](int c) {
        const int ka = (c & 3) * 64 + ((c >= 8) ? 256 : 0);              // A: hi,hi,lo
        const int kb = (c & 3) * 64 + ((c >= 4 && c < 8) ? 256 : 0);     // B: hi,lo,hi
        const uint32_t base = smb + (c % 3) * STAGE_B;
#pragma unroll
        for (int k = 0; k < 4; k++)
            cp16(base + soff0 + k * 4096, baseA + (size_t)k * 32 * KHL + ka);
#pragma unroll
        for (int k = 4; k < 8; k++)
            cp16(base + soff0 + k * 4096, baseB + (size_t)(k - 4) * 32 * KHL + kb);
        asm volatile("cp.async.commit_group;" ::: "memory");
    };

    float acc[2][8][4];
#pragma unroll
    for (int mi = 0; mi < 2; mi++)
#pragma unroll
        for (int ni = 0; ni < 8; ni++)
#pragma unroll
            for (int v = 0; v < 4; v++) acc[mi][ni][v] = 0.f;

    issue(0); issue(1);

    for (int c = 0; c < NCH; c++) {
        if (c < NCH - 1) asm volatile("cp.async.wait_group 1;" ::: "memory");
        else             asm volatile("cp.async.wait_group 0;" ::: "memory");
        __syncthreads();
        if (c + 2 < NCH) issue(c + 2);

        const uint32_t Ab = smb + (c % 3) * STAGE_B;
        const uint32_t Bb = Ab + 16384;

#pragma unroll
        for (int k16 = 0; k16 < 4; k16++) {
            uint32_t afr[2][4], bfr[8][2];
#pragma unroll
            for (int mi = 0; mi < 2; mi++) {
                int R = wm * 32 + mi * 16 + (lane & 15);
                int ul = k16 * 2 + (lane >> 4);
                ldmx4(afr[mi], Ab + R * 128 + ((ul ^ (R & 7)) * 16));
            }
#pragma unroll
            for (int np = 0; np < 4; np++) {
                int RB = wn * 64 + np * 16 + ((lane >> 4) << 3) + (lane & 7);
                int ul = k16 * 2 + ((lane >> 3) & 1);
                uint32_t r[4];
                ldmx4(r, Bb + RB * 128 + ((ul ^ (RB & 7)) * 16));
                bfr[np * 2][0] = r[0]; bfr[np * 2][1] = r[1];
                bfr[np * 2 + 1][0] = r[2]; bfr[np * 2 + 1][1] = r[3];
            }
#pragma unroll
            for (int mi = 0; mi < 2; mi++)
#pragma unroll
                for (int ni = 0; ni < 8; ni++)
                    mma16816(acc[mi][ni], afr[mi], bfr[ni]);
        }
        // no trailing barrier — next iteration's post-wait __syncthreads orders stage reuse
    }

    // ---- row fold: rows of tile I over all 128 cols of tile J ----
    int gi[4]; float sqi[4];
#pragma unroll
    for (int mi = 0; mi < 2; mi++)
#pragma unroll
        for (int h = 0; h < 2; h++) {
            int s2 = mi * 2 + h;
            gi[s2] = i0 + wm * 32 + mi * 16 + (lane >> 2) + h * 8;
            sqi[s2] = g_sq[b * NN + gi[s2]];
        }
    float t5[4][5];
#pragma unroll
    for (int s2 = 0; s2 < 4; s2++)
#pragma unroll
        for (int q = 0; q < 5; q++) t5[s2][q] = INFINITY;

#pragma unroll
    for (int ni = 0; ni < 8; ni++)
#pragma unroll
        for (int cc = 0; cc < 2; cc++) {
            int gj = j0 + wn * 64 + ni * 8 + (lane & 3) * 2 + cc;
            float sqj = __ldg(&g_sq[b * NN + gj]);
#pragma unroll
            for (int mi = 0; mi < 2; mi++)
#pragma unroll
                for (int h = 0; h < 2; h++) {
                    int s2 = mi * 2 + h;
                    float G = acc[mi][ni][h * 2 + cc];
                    float v = __fsub_rn(__fadd_rn(sqi[s2], sqj), __fmul_rn(2.0f, G));
                    v = fmaxf(v, 0.0f);
                    if (gj == gi[s2]) v = INFINITY;
                    ins5(t5[s2], v);
                }
        }

    // ---- merge 8 owners per row, write g_part slot J ----
    __syncthreads();   // all warps done reading smem stages before reuse
    float* MS = (float*)sm;   // 128 rows x 8 owners x 5 = 20KB
    const int owner = wn * 4 + (lane & 3);
#pragma unroll
    for (int s2 = 0; s2 < 4; s2++) {
        int rloc = gi[s2] - i0;
#pragma unroll
        for (int q = 0; q < 5; q++) MS[rloc * 40 + owner * 5 + q] = t5[s2][q];
    }
    __syncthreads();
    if (tid < 128) {
        float best[5] = {INFINITY, INFINITY, INFINITY, INFINITY, INFINITY};
        for (int k = 0; k < 40; k++) ins5(best, MS[tid * 40 + k]);
        size_t o = ((size_t)J * BN * NN + (size_t)(b * NN + i0 + tid)) * 5;
#pragma unroll
        for (int q = 0; q < 5; q++) g_part[o + q] = best[q];
    }

    // ---- column fold (off-diagonal only): per-column top-5 over 128 rows ----
    if (J > I) {
        __syncthreads();
        float* BUF = (float*)sm;           // [128 cols][129]
        float* CM  = (float*)(sm + CM_OFF); // [128 cols][10]
#pragma unroll
        for (int ni = 0; ni < 8; ni++)
#pragma unroll
            for (int cc = 0; cc < 2; cc++) {
                int cl = wn * 64 + ni * 8 + (lane & 3) * 2 + cc;
                int gj = j0 + cl;
                float sqj = __ldg(&g_sq[b * NN + gj]);
#pragma unroll
                for (int mi = 0; mi < 2; mi++)
#pragma unroll
                    for (int h = 0; h < 2; h++) {
                        int s2 = mi * 2 + h;
                        int rl = gi[s2] - i0;
                        float G = acc[mi][ni][h * 2 + cc];
                        float v = __fsub_rn(__fadd_rn(sqi[s2], sqj), __fmul_rn(2.0f, G));
                        v = fmaxf(v, 0.0f);
                        BUF[cl * BUF_STRIDE + rl] = v;
                    }
            }
        __syncthreads();
        {
            const int col = tid & 127;
            const int part = tid >> 7;     // 0..1, rows part*64..+64
            float best[5] = {INFINITY, INFINITY, INFINITY, INFINITY, INFINITY};
            const float* bp = BUF + col * BUF_STRIDE + part * 64;
#pragma unroll
            for (int r = 0; r < 64; r++) ins5(best, bp[r]);
#pragma unroll
            for (int q = 0; q < 5; q++) CM[col * 10 + part * 5 + q] = best[q];
        }
        __syncthreads();
        if (tid < 128) {
            float best[5] = {INFINITY, INFINITY, INFINITY, INFINITY, INFINITY};
#pragma unroll
            for (int k = 0; k < 10; k++) ins5(best, CM[tid * 10 + k]);
            size_t o = ((size_t)(32 + I) * BN * NN + (size_t)(b * NN + j0 + tid)) * 5;
#pragma unroll
            for (int q = 0; q < 5; q++) g_part[o + q] = best[q];
        }
    }
}

// ---------------- kernel C2: merge partial top-5 lists (4 threads/row + shfl) ----------------
__global__ void merge_kernel() {
    int t = blockIdx.x * 256 + threadIdx.x;
    int r = t >> 2;                 // b*NN + i
    int par = t & 3;
    int i = r & (NN - 1);
    int T = i >> 7;
    float best[5] = {INFINITY, INFINITY, INFINITY, INFINITY, INFINITY};
    // 32 live slots: k<32-T -> row-fold slot T+k ; else col-fold slot 32+(k-(32-T))
    for (int k = par; k < 32; k += 4) {
        int slot = (k < 32 - T) ? (T + k) : (32 + k - (32 - T));
        size_t o = ((size_t)slot * BN * NN + r) * 5;
#pragma unroll
        for (int q = 0; q < 5; q++) ins5(best, g_part[o + q]);
    }
    float ob[5];
#pragma unroll
    for (int q = 0; q < 5; q++) ob[q] = __shfl_xor_sync(0xffffffffu, best[q], 1);
#pragma unroll
    for (int q = 0; q < 5; q++) ins5(best, ob[q]);
#pragma unroll
    for (int q = 0; q < 5; q++) ob[q] = __shfl_xor_sync(0xffffffffu, best[q], 2);
#pragma unroll
    for (int q = 0; q < 5; q++) ins5(best, ob[q]);
    if (par == 0) g_dk2[r] = best[4];
}

// ---------------- threefry2x32, key = (0, 42) ----------------
__device__ __forceinline__ uint2 threefry_0_42(unsigned x0, unsigned x1) {
    const unsigned ks0 = 0u, ks1 = 42u;
    const unsigned ks2 = 0x1BD11BDAu ^ 42u;
    x0 += ks0; x1 += ks1;
#define ROTL(v, d) (((v) << (d)) | ((v) >> (32 - (d))))
#define RND(r) { x0 += x1; x1 = ROTL(x1, r); x1 ^= x0; }
    RND(13) RND(15) RND(26) RND(6)  x0 += ks1; x1 += ks2 + 1u;
    RND(17) RND(29) RND(16) RND(24) x0 += ks2; x1 += ks0 + 2u;
    RND(13) RND(15) RND(26) RND(6)  x0 += ks0; x1 += ks1 + 3u;
    RND(17) RND(29) RND(16) RND(24) x0 += ks1; x1 += ks2 + 4u;
    RND(13) RND(15) RND(26) RND(6)  x0 += ks2; x1 += ks0 + 5u;
#undef RND
#undef ROTL
    return make_uint2(x0, x1);
}

// ---------------- kernel D1: per-chunk scores + top-256 candidates ----------------
__global__ void score_chunk_kernel() {
    __shared__ unsigned long long keys[SCHUNK];
    const int b = blockIdx.y;
    const int ch = blockIdx.x;
    const int tid = threadIdx.x; // 512
    const float TINY = 1.17549435e-38f;

    for (int t = tid; t < SCHUNK; t += 512) {
        int n = ch * SCHUNK + t;
        int jf = b * NN + n;
        uint2 y = threefry_0_42(0u, (unsigned)jf);
        unsigned bits = y.x ^ y.y;
        float u = __uint_as_float((bits >> 9) | 0x3f800000u) - 1.0f;
        float val = fmaxf(TINY, __fadd_rn(u, TINY));
        float g = -logf(-logf(val));
        float w = sqrtf(__fadd_rn(g_dk2[jf], 1e-12f));
        float score = __fadd_rn(logf(__fadd_rn(w, 1e-12f)), g);
        unsigned sb = __float_as_uint(score);
        unsigned mono = (sb & 0x80000000u) ? ~sb : (sb | 0x80000000u);
        keys[t] = ((unsigned long long)(~mono) << 32) | (unsigned)n;  // asc = desc score, ties -> low idx
    }
    __syncthreads();

    for (int k = 2; k <= SCHUNK; k <<= 1) {
        for (int j = k >> 1; j > 0; j >>= 1) {
            for (int i = tid; i < SCHUNK; i += 512) {
                int ixj = i ^ j;
                if (ixj > i) {
                    bool up = ((i & k) == 0);
                    unsigned long long a = keys[i], c = keys[ixj];
                    if ((a > c) == up) { keys[i] = c; keys[ixj] = a; }
                }
            }
            __syncthreads();
        }
    }
    if (tid < SAMPK) g_cand[(b * NCHUNK + ch) * SAMPK + tid] = keys[tid];
}

// ---------------- kernel D2: merge candidates, final top-256 ----------------
__global__ void final_sort_kernel() {
    __shared__ unsigned long long keys[NCHUNK * SAMPK];  // 1024
    const int b = blockIdx.x;
    const int tid = threadIdx.x; // 512
    const int NC = NCHUNK * SAMPK;

    for (int t = tid; t < NC; t += 512) keys[t] = g_cand[b * NC + t];
    __syncthreads();

    for (int k = 2; k <= NC; k <<= 1) {
        for (int j = k >> 1; j > 0; j >>= 1) {
            for (int i = tid; i < NC; i += 512) {
                int ixj = i ^ j;
                if (ixj > i) {
                    bool up = ((i & k) == 0);
                    unsigned long long a = keys[i], c = keys[ixj];
                    if ((a > c) == up) { keys[i] = c; keys[ixj] = a; }
                }
            }
            __syncthreads();
        }
    }
    if (tid < SAMPK) g_sidx[b * SAMPK + tid] = (int)(keys[tid] & 0xffffffffu);
}

// ---------------- kernel E: vectorized gather + tail zero ----------------
__global__ void gather_kernel(const float* __restrict__ x, float* __restrict__ out, int out_size) {
    const long SAMPV = (long)BN * SAMPK * DD / 4;   // float4 count
    long gid = (long)blockIdx.x * 256 + threadIdx.x;
    if (gid < SAMPV) {
        int d4 = (int)(gid & 63);
        int samp = (int)(gid >> 6);          // bb*256 + s
        int s = samp & 255;
        int bb = samp >> 8;
        int idx = g_sidx[bb * SAMPK + s];
        float4 v = *(const float4*)(x + ((size_t)bb * NN + idx) * DD + d4 * 4);
        *(float4*)(out + gid * 4) = v;
    } else {
        long t = (long)BN * SAMPK * DD + (gid - SAMPV);
        if (t < out_size) out[t] = 0.0f;
    }
}

// ---------------- launch ----------------
extern "C" void kernel_launch(void* const* d_in, const int* in_sizes, int n_in,
                              void* d_out, int out_size) {
    const float* x = (const float*)d_in[0];
    float* out = (float*)d_out;

    static bool configured = false;
    if (!configured) {
        cudaFuncSetAttribute(knn_sym_kernel, cudaFuncAttributeMaxDynamicSharedMemorySize, KNN_SMEM);
        configured = true;
    }

    cvtsq_kernel<<<BN * NN / 8, 256>>>(x);

    dim3 g1(NSTRIPE, BN);
    knn_sym_kernel<<<g1, 256, KNN_SMEM>>>();

    merge_kernel<<<BN * NN * 4 / 256, 256>>>();

    dim3 gs(NCHUNK, BN);
    score_chunk_kernel<<<gs, 512>>>();
    final_sort_kernel<<<BN, 512>>>();

    long samp = (long)BN * SAMPK * DD;
    long work = samp / 4 + (out_size > samp ? out_size - samp : 0);
    gather_kernel<<<(unsigned)((work + 255) / 256), 256>>>(x, out, out_size);
}